// round 3
// baseline (speedup 1.0000x reference)
#include <cuda_runtime.h>
#include <math.h>

#define NB    8
#define NPTS  4096
#define KNNK  16
#define KK    17          // K+1 (self included, dropped at merge)
#define PPB   64          // query points per block
#define CH    4           // candidate chunks (threads per query point)
#define KNN_THREADS 256   // PPB*CH

#define INF_F __int_as_float(0x7f800000)

// ---- scratch (device globals; no allocations allowed) ----
__device__ float g_std24[24];
__device__ float g_scal[8];                 // S1, 1/S1, blend, Q1, cos(d1), sin(d1), d1
__device__ float g_lstd[NB * NPTS * 3];
__device__ float g_curv[NB * NPTS];
__device__ float g_curvmean[NB];

// ============================================================
// Kernel 1: per-(batch,dim) std over N (ddof=1), 24 blocks
// ============================================================
__global__ void bd_std_kernel(const float* __restrict__ xyz) {
    __shared__ double ssum[256];
    __shared__ double ssq[256];
    int bd = blockIdx.x;
    const float* p = xyz + (bd / 3) * NPTS * 3 + (bd % 3);
    double s = 0.0, s2 = 0.0;
    for (int i = threadIdx.x; i < NPTS; i += 256) {
        double v = (double)p[3 * i];
        s += v; s2 += v * v;
    }
    ssum[threadIdx.x] = s; ssq[threadIdx.x] = s2;
    __syncthreads();
    for (int off = 128; off > 0; off >>= 1) {
        if (threadIdx.x < off) {
            ssum[threadIdx.x] += ssum[threadIdx.x + off];
            ssq[threadIdx.x]  += ssq[threadIdx.x + off];
        }
        __syncthreads();
    }
    if (threadIdx.x == 0) {
        double mean = ssum[0] / NPTS;
        double var  = (ssq[0] - (double)NPTS * mean * mean) / (NPTS - 1);
        g_std24[bd] = (float)sqrt(var > 0.0 ? var : 0.0);
    }
}

// ============================================================
// Kernel 2: global scalars (gstd, sigma, blend, recurrence consts)
// ============================================================
__global__ void consts_kernel() {
    if (threadIdx.x != 0) return;
    double g = 0.0;
    for (int i = 0; i < 24; i++) g += (double)g_std24[i];
    g /= 24.0;
    double asig  = 0.3 * (1.0 + g);
    double S1    = asig + 1e-6;
    double blend = 1.0 / (1.0 + exp(-(g - 0.1) * 10.0));
    double h  = 1.0 / 22.0;
    double d1 = h / S1;
    g_scal[0] = (float)S1;
    g_scal[1] = (float)(1.0 / S1);
    g_scal[2] = (float)blend;
    g_scal[3] = (float)exp(-d1 * d1);   // Q1
    g_scal[4] = (float)cos(d1);
    g_scal[5] = (float)sin(d1);
    g_scal[6] = (float)d1;
}

// ============================================================
// Kernel 3: fused kNN + covariance + eigen (curv) + lstd
// grid (NPTS/PPB, NB), 256 threads, ~98KB dyn smem
// ============================================================
__global__ void __launch_bounds__(KNN_THREADS, 2)
knn_kernel(const float* __restrict__ xyz) {
    extern __shared__ char smraw[];
    float4* pts = (float4*)smraw;                               // 4096 * 16B
    float*  md  = (float*)(smraw + NPTS * 16);                  // 256*17 floats
    int*    mi  = (int*)(smraw + NPTS * 16 + KNN_THREADS * KK * 4);

    int b = blockIdx.y;
    const float* base = xyz + (size_t)b * NPTS * 3;

    // load batch points + squared norms (same formula family as reference)
    for (int i = threadIdx.x; i < NPTS; i += KNN_THREADS) {
        float x = base[3 * i], y = base[3 * i + 1], z = base[3 * i + 2];
        pts[i] = make_float4(x, y, z, fmaf(z, z, fmaf(y, y, x * x)));
    }
    __syncthreads();

    int tid = threadIdx.x;
    int p   = tid >> 2;      // query point within block
    int s   = tid & 3;       // candidate chunk
    int qi  = blockIdx.x * PPB + p;
    float4 q = pts[qi];

    float dd[KK]; int di[KK];
#pragma unroll
    for (int k = 0; k < KK; k++) { dd[k] = INF_F; di[k] = 0x7fffffff; }

    // scan candidates j = 4*step + s (warp reads 4 consecutive float4 -> bcast)
    for (int step = 0; step < NPTS / CH; step++) {
        int j = (step << 2) + s;
        float4 c = pts[j];
        float dot = fmaf(q.z, c.z, fmaf(q.y, c.y, q.x * c.x));
        float d2  = (q.w + c.w) - 2.0f * dot;   // matches ref: sq_i + sq_j - 2 dot
        if (d2 < dd[KK - 1]) {
            // fully-unrolled predicated sorted insert (no dynamic indexing)
#pragma unroll
            for (int k = KK - 1; k >= 0; k--) {
                bool lt = d2 < dd[k];
                bool fromAbove = (k > 0) ? (d2 < dd[k - 1]) : false;
                if (lt) {
                    dd[k] = fromAbove ? dd[k - 1] : d2;
                    di[k] = fromAbove ? di[k - 1] : j;
                }
            }
        }
    }

    // dump partial lists
#pragma unroll
    for (int k = 0; k < KK; k++) {
        md[tid * KK + k] = dd[k];
        mi[tid * KK + k] = di[k];
    }
    __syncthreads();

    // one thread per query point: 4-way merge (lexicographic (d2, idx) like top_k),
    // drop first pick (self), accumulate neighbor stats
    if (tid < PPB) {
        const float* L0 = md + (tid * CH + 0) * KK;
        const float* L1 = md + (tid * CH + 1) * KK;
        const float* L2 = md + (tid * CH + 2) * KK;
        const float* L3 = md + (tid * CH + 3) * KK;
        const int*   I0 = mi + (tid * CH + 0) * KK;
        const int*   I1 = mi + (tid * CH + 1) * KK;
        const int*   I2 = mi + (tid * CH + 2) * KK;
        const int*   I3 = mi + (tid * CH + 3) * KK;
        int c0 = 0, c1 = 0, c2 = 0, c3 = 0;
        double sx = 0, sy = 0, sz = 0;
        double sxx = 0, syy = 0, szz = 0, sxy = 0, sxz = 0, syz = 0;

        for (int k = 0; k < KK; k++) {
            float h0 = L0[c0], h1 = L1[c1], h2 = L2[c2], h3 = L3[c3];
            int   i0 = I0[c0], i1 = I1[c1], i2 = I2[c2], i3 = I3[c3];
            float bv = h0; int bi = i0; int bs = 0;
            if (h1 < bv || (h1 == bv && i1 < bi)) { bv = h1; bi = i1; bs = 1; }
            if (h2 < bv || (h2 == bv && i2 < bi)) { bv = h2; bi = i2; bs = 2; }
            if (h3 < bv || (h3 == bv && i3 < bi)) { bv = h3; bi = i3; bs = 3; }
            c0 += (bs == 0); c1 += (bs == 1); c2 += (bs == 2); c3 += (bs == 3);
            if (k > 0) {   // k==0 is self (or nearest tie), dropped like ref idx[:,:,1:]
                float4 nb = pts[bi];
                double nx = nb.x, ny = nb.y, nz = nb.z;
                sx += nx; sy += ny; sz += nz;
                sxx += nx * nx; syy += ny * ny; szz += nz * nz;
                sxy += nx * ny; sxz += nx * nz; syz += ny * nz;
            }
        }

        double mx = sx / 16.0, my = sy / 16.0, mz = sz / 16.0;
        double cxx = (sxx - 16.0 * mx * mx) / 15.0;
        double cyy = (syy - 16.0 * my * my) / 15.0;
        double czz = (szz - 16.0 * mz * mz) / 15.0;
        double cxy = (sxy - 16.0 * mx * my) / 15.0;
        double cxz = (sxz - 16.0 * mx * mz) / 15.0;
        double cyz = (syz - 16.0 * my * mz) / 15.0;

        // smallest eigenvalue of symmetric 3x3 (trigonometric closed form)
        double tr = cxx + cyy + czz;
        double qm = tr / 3.0;
        double aa = cxx - qm, bb = cyy - qm, cc = czz - qm;
        double p2 = aa * aa + bb * bb + cc * cc
                  + 2.0 * (cxy * cxy + cxz * cxz + cyz * cyz);
        double lmin;
        if (p2 <= 1e-300) {
            lmin = qm;
        } else {
            double pp  = sqrt(p2 / 6.0);
            double inv = 1.0 / pp;
            double b00 = aa * inv, b11 = bb * inv, b22 = cc * inv;
            double b01 = cxy * inv, b02 = cxz * inv, b12 = cyz * inv;
            double det = b00 * (b11 * b22 - b12 * b12)
                       - b01 * (b01 * b22 - b12 * b02)
                       + b02 * (b01 * b12 - b11 * b02);
            double r = 0.5 * det;
            r = r < -1.0 ? -1.0 : (r > 1.0 ? 1.0 : r);
            double phi = acos(r) * (1.0 / 3.0);
            lmin = qm + 2.0 * pp * cos(phi + 2.0943951023931953); // +2pi/3 -> min
        }

        int gi = b * NPTS + blockIdx.x * PPB + tid;
        g_curv[gi] = (float)(lmin / (tr + 1e-6));
        g_lstd[gi * 3 + 0] = (float)sqrt(cxx > 0.0 ? cxx : 0.0);
        g_lstd[gi * 3 + 1] = (float)sqrt(cyy > 0.0 ? cyy : 0.0);
        g_lstd[gi * 3 + 2] = (float)sqrt(czz > 0.0 ? czz : 0.0);
    }
}

// ============================================================
// Kernel 4: per-batch curvature mean
// ============================================================
__global__ void curvmean_kernel() {
    __shared__ double sh[256];
    int b = blockIdx.x;
    double s = 0.0;
    for (int i = threadIdx.x; i < NPTS; i += 256) s += (double)g_curv[b * NPTS + i];
    sh[threadIdx.x] = s;
    __syncthreads();
    for (int off = 128; off > 0; off >>= 1) {
        if (threadIdx.x < off) sh[threadIdx.x] += sh[threadIdx.x + off];
        __syncthreads();
    }
    if (threadIdx.x == 0) g_curvmean[b] = (float)(sh[0] / NPTS);
}

// ============================================================
// Kernel 5: embedding via geometric/rotation recurrences
// block = 96 threads (32 points x 3 dims), grid (NPTS/32, NB)
// ============================================================
__global__ void __launch_bounds__(96)
embed_kernel(const float* __restrict__ xyz, float* __restrict__ out) {
    __shared__ float sm[32][129];   // +1 pad -> conflict-free
    int tid = threadIdx.x;
    int p = tid & 31;      // point within tile
    int d = tid >> 5;      // dim (warp-uniform)
    int b = blockIdx.y;
    int n0 = blockIdx.x * 32;
    int gp = b * NPTS + n0 + p;

    float x    = xyz[(size_t)gp * 3 + d];
    float lstd = g_lstd[(size_t)gp * 3 + d];
    float curv = g_curv[gp];
    float cm   = g_curvmean[b];
    float w    = 1.0f / (1.0f + __expf(-10.0f * (curv - cm)));

    float invS1 = g_scal[1], blend = g_scal[2];
    float Q1 = g_scal[3], cd1 = g_scal[4], sd1 = g_scal[5], d1 = g_scal[6];

    float Aw = w * blend;            // weight for gaussian-1
    float Bw = w * (1.0f - blend);   // weight for cos
    float Cw = 1.0f - w;             // weight for gaussian-2

    const float h   = 0.045454545454545456f;   // 1/22
    const float fv0 = -0.9545454545454546f;    // -21/22 (FEAT_VAL[0]); FEAT_VAL[42] = -fv0

    float S2   = fmaf(0.3f, lstd, 0.3f) + 1e-6f;   // 0.3*(1+lstd)+eps
    float inv2 = 1.0f / S2;
    float d2s  = h * inv2;
    float Q2   = __expf(-d2s * d2s);

    bool  up  = (x <= 0.0f);                 // seed at boundary nearest x
    float sgn = up ? 1.0f : -1.0f;
    int   f   = up ? 0 : 42;
    int   df  = up ? 1 : -1;
    float fva = up ? fv0 : -fv0;

    float t1 = (x - fva) * invS1;
    float t2 = (x - fva) * inv2;
    float G1 = __expf(-0.5f * t1 * t1);
    float G2 = __expf(-0.5f * t2 * t2);
    float r1 = __expf(sgn * d1  * (t1 - sgn * 0.5f * d1));
    float r2 = __expf(sgn * d2s * (t2 - sgn * 0.5f * d2s));
    float cc = __cosf(t1);
    float sn = __sinf(t1);
    float sd = up ? sd1 : -sd1;   // rotation direction

    for (int it = 0; it < 43; it++) {
        float val = fmaf(Aw, G1, fmaf(Bw, cc, Cw * G2));
        int col;
        if (d < 2) col = d * 43 + f;
        else       col = (f < 41) ? (86 + f) : ((f == 42) ? 127 : -1);  // OUT_IDX skips g=127
        if (col >= 0) sm[p][col] = val;
        G1 *= r1; r1 *= Q1;
        G2 *= r2; r2 *= Q2;
        float cn  = fmaf(cc, cd1,  sn * sd);
        float sn2 = fmaf(sn, cd1, -cc * sd);
        cc = cn; sn = sn2;
        f += df;
    }
    __syncthreads();

    float* ob = out + ((size_t)b * NPTS + n0) * 128;
    for (int i = tid; i < 32 * 128; i += 96)
        ob[i] = sm[i >> 7][i & 127];
}

// ============================================================
extern "C" void kernel_launch(void* const* d_in, const int* in_sizes, int n_in,
                              void* d_out, int out_size) {
    const float* xyz = (const float*)d_in[0];
    float* out = (float*)d_out;
    (void)in_sizes; (void)n_in; (void)out_size;

    const int knn_smem = NPTS * 16 + 2 * KNN_THREADS * KK * 4;   // 100352 B
    cudaFuncSetAttribute(knn_kernel, cudaFuncAttributeMaxDynamicSharedMemorySize, knn_smem);

    bd_std_kernel<<<24, 256>>>(xyz);
    consts_kernel<<<1, 32>>>();
    dim3 kg(NPTS / PPB, NB);
    knn_kernel<<<kg, KNN_THREADS, knn_smem>>>(xyz);
    curvmean_kernel<<<NB, 256>>>();
    dim3 eg(NPTS / 32, NB);
    embed_kernel<<<eg, 96>>>(xyz, out);
}